// round 12
// baseline (speedup 1.0000x reference)
#include <cuda_runtime.h>
#include <cstddef>

#define NB 1024          // 32*32 nodes per time slice
#define NT 9
#define TN (NT * NB)     // 9216
#define RPC 4            // rows per CTA (all in same block row; 1024%4==0)
#define W0MAX 136        // slice-t0 window nodes (p0-66 .. p0+69)
#define A1N 18           // slice-i window: 3 segments x 6 nodes
#define BSTRIDE 272      // per-row band: [0..135]=D(d+66), [136..203]=L(d+33), [204..271]=R(d+33)

// ---------------------------------------------------------------------------
// Per-node 9-point stencil coefficients of A at time slice ts.
// j = (dy+1)*3 + (dx+1); Dirichlet-invalid moves = exact 0.
// ---------------------------------------------------------------------------
__device__ __forceinline__ void coef9(const float* __restrict__ kappa,
                                      const float* __restrict__ m,
                                      const float* __restrict__ H,
                                      int n, int ts, float* c) {
    float kap = kappa[n * NT + ts];
    float k2  = kap * kap;
    float m1  = m[(0 * NB + n) * NT + ts];
    float m2  = m[(1 * NB + n) * NT + ts];
    float H11 = H[(0 * NB + n) * NT + ts];
    float H12 = H[(1 * NB + n) * NT + ts];
    float H22 = H[(3 * NB + n) * NT + ts];

    int ix = n & 31, iy = n >> 5;
    bool xm = ix > 0, xp = ix < 31, ym = iy > 0, yp = iy < 31;

    c[4] = k2 + 2.0f * H11 + 2.0f * H22;
    c[5] = xp         ? ( 0.5f * m1 - H11) : 0.0f;
    c[3] = xm         ? (-0.5f * m1 - H11) : 0.0f;
    c[7] = yp         ? ( 0.5f * m2 - H22) : 0.0f;
    c[1] = ym         ? (-0.5f * m2 - H22) : 0.0f;
    c[8] = (xp && yp) ? (-0.5f * H12)      : 0.0f;
    c[2] = (xp && ym) ? ( 0.5f * H12)      : 0.0f;
    c[6] = (xm && yp) ? ( 0.5f * H12)      : 0.0f;
    c[0] = (xm && ym) ? (-0.5f * H12)      : 0.0f;
}

// ---------------------------------------------------------------------------
// Single self-contained kernel: one CTA per 4 adjacent output rows.
//   1) stream non-band column blocks for all 4 rows (zeros)
//   2) build coef windows: slice t0 (<=136 nodes) + slice i (18 nodes)
//   3) 4x43 threads compute band slots into direct-indexed pre-zeroed arrays
//   4) stream 3 band column blocks per row
// Every output byte written exactly once; no inter-CTA dependency.
// ---------------------------------------------------------------------------
__global__ __launch_bounds__(256)
void k_all(const float* __restrict__ kappa,
           const float* __restrict__ m,
           const float* __restrict__ H,
           float* __restrict__ out) {
    int bc  = blockIdx.x;               // 0..2303
    int r0  = bc << 2;                  // first row
    int i   = r0 >> 10;                 // block row (rows never straddle)
    int p0  = r0 & (NB - 1);
    int tid = threadIdx.x;
    float4 z = make_float4(0.f, 0.f, 0.f, 0.f);

    // ---- 1) zero blocks for all rows ----
#pragma unroll
    for (int rr = 0; rr < RPC; rr++) {
        float4* rowp = (float4*)(out + (size_t)(r0 + rr) * TN);
#pragma unroll
        for (int j = 0; j < 9; j++) {
            if (j < i - 1 || j > i + 1)
                __stcs(rowp + j * 256 + tid, z);
        }
    }

    // ---- 2) build coefficient windows + zero band arrays ----
    __shared__ float sA0[W0MAX * 9];    // slice t0
    __shared__ float sA1[A1N * 9];      // slice i, 3 segments x 6 nodes
    __shared__ float sBand[RPC][BSTRIDE];

    int t0    = (i == 0) ? 0 : (i - 1);
    int wbase = max(0, p0 - 66);
    int whi   = min(NB, p0 + RPC - 1 + 67);
    int cnt0  = whi - wbase;
    bool needA1 = (i >= 1 && i <= 7);

    for (int k = tid; k < RPC * BSTRIDE; k += 256)
        ((float*)sBand)[k] = 0.0f;

    int tot = cnt0 + (needA1 ? A1N : 0);
    for (int k = tid; k < tot; k += 256) {
        float c[9];
        if (k < cnt0) {
            coef9(kappa, m, H, wbase + k, t0 + 1, c);
            float* dst = sA0 + k * 9;
#pragma unroll
            for (int j = 0; j < 9; j++) dst[j] = c[j];
        } else {
            int kk = k - cnt0;                  // 0..17
            int seg = kk / 6;
            int node = p0 + seg * 32 - 33 + (kk - seg * 6);
            float* dst = sA1 + kk * 9;
            if (node >= 0 && node < NB) {
                coef9(kappa, m, H, node, i + 1, c);
#pragma unroll
                for (int j = 0; j < 9; j++) dst[j] = c[j];
            } else {
#pragma unroll
                for (int j = 0; j < 9; j++) dst[j] = 0.0f;
            }
        }
    }
    __syncthreads();

    // ---- 3) band slot computation: warps 0..7, rr = tid>>6, s = tid&63 ----
    int rr = tid >> 6;                  // 0..3
    int s  = tid & 63;                  // slot 0..42 active

    if (s < 43) {
        int p = p0 + rr;
        if (s < 25) {
            // diag slot: delta = ey*32 + ex
            int ey = s / 5 - 2, ex = s % 5 - 2;
            int delta = ey * 32 + ex;
            int q = p + delta;
            if (q >= 0 && q < NB) {
                float v;
                if (i == 0) {
                    // (A^T A)[p][q] = sum_r A[r][p]*A[r][q]
                    float acc = 0.0f;
#pragma unroll
                    for (int j = 0; j < 9; j++) {
                        int dy = j / 3 - 1, dx = j % 3 - 1;
                        int rn = p + dy * 32 + dx;
                        if (rn < 0 || rn >= NB) continue;
                        int ddy = ey - dy, ddx = ex - dx;
                        if (ddy < -1 || ddy > 1 || ddx < -1 || ddx > 1) continue;
                        int j2 = (ddy + 1) * 3 + (ddx + 1);
                        acc += sA0[(rn - wbase) * 9 + (8 - j)] *
                               sA0[(rn - wbase) * 9 + j2];
                    }
                    v = acc + ((delta == 0) ? 1.05f : 0.0f);
                } else {
                    // 0.5*(MM + MM^T)[p][q],  MM = (I+A)^2 on slice t0
                    float mmpq = 0.0f, mmqp = 0.0f;
#pragma unroll
                    for (int j = 0; j < 9; j++) {
                        int dy = j / 3 - 1, dx = j % 3 - 1;
                        {   // p -> rn -> q
                            int rn = p + dy * 32 + dx;
                            int ddy = ey - dy, ddx = ex - dx;
                            if (rn >= 0 && rn < NB &&
                                ddy >= -1 && ddy <= 1 && ddx >= -1 && ddx <= 1) {
                                int j2 = (ddy + 1) * 3 + (ddx + 1);
                                float a = sA0[(p - wbase) * 9 + j]   + ((j  == 4) ? 1.0f : 0.0f);
                                float b = sA0[(rn - wbase) * 9 + j2] + ((j2 == 4) ? 1.0f : 0.0f);
                                mmpq += a * b;
                            }
                        }
                        {   // q -> sn -> p
                            int sn = q + dy * 32 + dx;
                            int ddy = -ey - dy, ddx = -ex - dx;
                            if (sn >= 0 && sn < NB &&
                                ddy >= -1 && ddy <= 1 && ddx >= -1 && ddx <= 1) {
                                int j2 = (ddy + 1) * 3 + (ddx + 1);
                                float a = sA0[(q - wbase) * 9 + j]   + ((j  == 4) ? 1.0f : 0.0f);
                                float b = sA0[(sn - wbase) * 9 + j2] + ((j2 == 4) ? 1.0f : 0.0f);
                                mmqp += a * b;
                            }
                        }
                    }
                    v = 0.5f * (mmpq + mmqp) +
                        ((delta == 0) ? ((i < 8) ? 1.05f : 0.05f) : 0.0f);
                }
                sBand[rr][delta + 66] = v;
            }
        } else if (s < 34) {
            // left offdiag (slice t0 = i-1): -0.5*(B + B^T)[p][q]
            int j = s - 25;
            int dy = j / 3 - 1, dx = j % 3 - 1;
            int delta = dy * 32 + dx;
            int q = p + delta;
            if (i > 0 && q >= 0 && q < NB) {
                float add = (j == 4) ? 2.0f : 0.0f;
                float v = -0.5f * (sA0[(p - wbase) * 9 + j] +
                                   sA0[(q - wbase) * 9 + (8 - j)] + add);
                sBand[rr][136 + delta + 33] = v;
            }
        } else {
            // right offdiag (slice i): sA1 (18-node map) for 1<=i<=7, sA0 for i=0
            int j = s - 34;
            int dy = j / 3 - 1, dx = j % 3 - 1;
            int delta = dy * 32 + dx;
            int q = p + delta;
            if (i < 8 && q >= 0 && q < NB) {
                float a, b;
                if (i == 0) {
                    a = sA0[(p - wbase) * 9 + j];
                    b = sA0[(q - wbase) * 9 + (8 - j)];
                } else {
                    int offp = p - p0 + 33;     // 33..36 -> seg 1
                    int offq = q - p0 + 33;     // in [0,5]u[32,37]u[64,69]
                    int ip = (offp >> 5) * 6 + (offp & 31);
                    int iq = (offq >> 5) * 6 + (offq & 31);
                    a = sA1[ip * 9 + j];
                    b = sA1[iq * 9 + (8 - j)];
                }
                float add = (j == 4) ? 2.0f : 0.0f;
                float v = -0.5f * (a + b + add);
                sBand[rr][204 + delta + 33] = v;
            }
        }
    }
    __syncthreads();

    // ---- 4) band blocks for all rows ----
    int q0 = tid << 2;
#pragma unroll
    for (int rr2 = 0; rr2 < RPC; rr2++) {
        int p = p0 + rr2;
        float4* rowp = (float4*)(out + (size_t)(r0 + rr2) * TN);
        const float* bd = sBand[rr2];
        int d0 = q0 - p;

        {   // diag block i: D[d+66], valid d in [-66,66]
            float4 v = z;
            if (d0 + 3 >= -66 && d0 <= 66) {
                v.x = ((unsigned)(d0 + 66) <= 132u) ? bd[d0 + 66] : 0.0f;
                v.y = ((unsigned)(d0 + 67) <= 132u) ? bd[d0 + 67] : 0.0f;
                v.z = ((unsigned)(d0 + 68) <= 132u) ? bd[d0 + 68] : 0.0f;
                v.w = ((unsigned)(d0 + 69) <= 132u) ? bd[d0 + 69] : 0.0f;
            }
            __stcs(rowp + i * 256 + tid, v);
        }
        if (i > 0) {                // left offdiag: L[d+33], d in [-33,33]
            float4 v = z;
            if (d0 + 3 >= -33 && d0 <= 33) {
                v.x = ((unsigned)(d0 + 33) <= 66u) ? bd[136 + d0 + 33] : 0.0f;
                v.y = ((unsigned)(d0 + 34) <= 66u) ? bd[136 + d0 + 34] : 0.0f;
                v.z = ((unsigned)(d0 + 35) <= 66u) ? bd[136 + d0 + 35] : 0.0f;
                v.w = ((unsigned)(d0 + 36) <= 66u) ? bd[136 + d0 + 36] : 0.0f;
            }
            __stcs(rowp + (i - 1) * 256 + tid, v);
        }
        if (i < 8) {                // right offdiag: R[d+33]
            float4 v = z;
            if (d0 + 3 >= -33 && d0 <= 33) {
                v.x = ((unsigned)(d0 + 33) <= 66u) ? bd[204 + d0 + 33] : 0.0f;
                v.y = ((unsigned)(d0 + 34) <= 66u) ? bd[204 + d0 + 34] : 0.0f;
                v.z = ((unsigned)(d0 + 35) <= 66u) ? bd[204 + d0 + 35] : 0.0f;
                v.w = ((unsigned)(d0 + 36) <= 66u) ? bd[204 + d0 + 36] : 0.0f;
            }
            __stcs(rowp + (i + 1) * 256 + tid, v);
        }
    }
}

// ---------------------------------------------------------------------------
// Launcher. Inputs: kappa, m, H, tau (unused). Output: fp32 [1, 9216, 9216].
// ---------------------------------------------------------------------------
extern "C" void kernel_launch(void* const* d_in, const int* in_sizes, int n_in,
                              void* d_out, int out_size) {
    const float* kappa = (const float*)d_in[0];
    const float* m     = (const float*)d_in[1];
    const float* H     = (const float*)d_in[2];
    float* out = (float*)d_out;

    k_all<<<TN / RPC, 256>>>(kappa, m, H, out);
}

// round 15
// speedup vs baseline: 1.0320x; 1.0320x over previous
#include <cuda_runtime.h>
#include <cstddef>

#define NB 1024          // 32*32 nodes per time slice
#define NT 9
#define TN (NT * NB)     // 9216
#define RPC 2            // rows per CTA (same block row)
#define NTH 512          // threads per CTA
#define W0MAX 134        // slice-t0 window nodes (p0-66 .. p0+67)
#define A1N 16           // slice-i window: 3 segments x 4 nodes + pad
#define BSTRIDE 272      // per-row band: [0..135]=D(d+66), [136..203]=L(d+33), [204..271]=R(d+33)

// ---------------------------------------------------------------------------
// Per-node 9-point stencil coefficients of A at time slice ts.
// j = (dy+1)*3 + (dx+1); Dirichlet-invalid moves = exact 0.
// ---------------------------------------------------------------------------
__device__ __forceinline__ void coef9(const float* __restrict__ kappa,
                                      const float* __restrict__ m,
                                      const float* __restrict__ H,
                                      int n, int ts, float* c) {
    float kap = kappa[n * NT + ts];
    float k2  = kap * kap;
    float m1  = m[(0 * NB + n) * NT + ts];
    float m2  = m[(1 * NB + n) * NT + ts];
    float H11 = H[(0 * NB + n) * NT + ts];
    float H12 = H[(1 * NB + n) * NT + ts];
    float H22 = H[(3 * NB + n) * NT + ts];

    int ix = n & 31, iy = n >> 5;
    bool xm = ix > 0, xp = ix < 31, ym = iy > 0, yp = iy < 31;

    c[4] = k2 + 2.0f * H11 + 2.0f * H22;
    c[5] = xp         ? ( 0.5f * m1 - H11) : 0.0f;
    c[3] = xm         ? (-0.5f * m1 - H11) : 0.0f;
    c[7] = yp         ? ( 0.5f * m2 - H22) : 0.0f;
    c[1] = ym         ? (-0.5f * m2 - H22) : 0.0f;
    c[8] = (xp && yp) ? (-0.5f * H12)      : 0.0f;
    c[2] = (xp && ym) ? ( 0.5f * H12)      : 0.0f;
    c[6] = (xm && yp) ? ( 0.5f * H12)      : 0.0f;
    c[0] = (xm && ym) ? (-0.5f * H12)      : 0.0f;
}

// ---------------------------------------------------------------------------
// Single self-contained kernel: one CTA (512 threads) per 2 adjacent rows.
// Thread tid owns (row = tid>>8, float4-column = tid&255): 9 stores each.
//   1) stream non-band column blocks (zeros)
//   2) build coef windows: slice t0 (<=134 nodes) + slice i (12 nodes)
//   3) 2x43 threads compute band slots into direct-indexed pre-zeroed arrays
//   4) stream 3 band column blocks
// Every output byte written exactly once; no inter-CTA dependency.
// ---------------------------------------------------------------------------
__global__ __launch_bounds__(NTH)
void k_all(const float* __restrict__ kappa,
           const float* __restrict__ m,
           const float* __restrict__ H,
           float* __restrict__ out) {
    int bc  = blockIdx.x;               // 0..4607
    int r0  = bc << 1;                  // first row
    int i   = r0 >> 10;                 // block row (rows never straddle)
    int p0  = r0 & (NB - 1);
    int tid = threadIdx.x;
    int rw  = tid >> 8;                 // this thread's row (0/1)
    int col = tid & 255;                // this thread's float4 column in block
    float4 z = make_float4(0.f, 0.f, 0.f, 0.f);

    float4* rowp = (float4*)(out + (size_t)(r0 + rw) * TN);

    // ---- 1) zero blocks for own row ----
#pragma unroll
    for (int j = 0; j < 9; j++) {
        if (j < i - 1 || j > i + 1)
            __stcs(rowp + j * 256 + col, z);
    }

    // ---- 2) build coefficient windows + zero band arrays ----
    __shared__ float sA0[W0MAX * 9];    // slice t0
    __shared__ float sA1[A1N * 9];      // slice i, 3 segments x 4 nodes
    __shared__ float sBand[RPC][BSTRIDE];

    int t0    = (i == 0) ? 0 : (i - 1);
    int wbase = max(0, p0 - 66);
    int whi   = min(NB, p0 + RPC - 1 + 67);
    int cnt0  = whi - wbase;
    bool needA1 = (i >= 1 && i <= 7);

    // NOTE: RPC*BSTRIDE = 544 > NTH, must grid-stride (R13 bug: single pass
    // left sBand[1][240..271] unzeroed).
    for (int k = tid; k < RPC * BSTRIDE; k += NTH)
        ((float*)sBand)[k] = 0.0f;

    int tot = cnt0 + (needA1 ? 12 : 0);
    if (tid < tot) {
        int k = tid;
        float c[9];
        if (k < cnt0) {
            coef9(kappa, m, H, wbase + k, t0 + 1, c);
            float* dst = sA0 + k * 9;
#pragma unroll
            for (int j = 0; j < 9; j++) dst[j] = c[j];
        } else {
            int kk = k - cnt0;                  // 0..11
            int seg = kk >> 2;
            int node = p0 + seg * 32 - 33 + (kk & 3);
            float* dst = sA1 + kk * 9;
            if (node >= 0 && node < NB) {
                coef9(kappa, m, H, node, i + 1, c);
#pragma unroll
                for (int j = 0; j < 9; j++) dst[j] = c[j];
            } else {
#pragma unroll
                for (int j = 0; j < 9; j++) dst[j] = 0.0f;
            }
        }
    }
    __syncthreads();

    // ---- 3) band slot computation: rr = tid>>8, s = tid&255 (0..42 active) ----
    {
        int rr = rw;
        int s  = col;
        if (s < 43) {
            int p = p0 + rr;
            if (s < 25) {
                // diag slot: delta = ey*32 + ex
                int ey = s / 5 - 2, ex = s % 5 - 2;
                int delta = ey * 32 + ex;
                int q = p + delta;
                if (q >= 0 && q < NB) {
                    float v;
                    if (i == 0) {
                        // (A^T A)[p][q] = sum_r A[r][p]*A[r][q]
                        float acc = 0.0f;
#pragma unroll
                        for (int j = 0; j < 9; j++) {
                            int dy = j / 3 - 1, dx = j % 3 - 1;
                            int rn = p + dy * 32 + dx;
                            if (rn < 0 || rn >= NB) continue;
                            int ddy = ey - dy, ddx = ex - dx;
                            if (ddy < -1 || ddy > 1 || ddx < -1 || ddx > 1) continue;
                            int j2 = (ddy + 1) * 3 + (ddx + 1);
                            acc += sA0[(rn - wbase) * 9 + (8 - j)] *
                                   sA0[(rn - wbase) * 9 + j2];
                        }
                        v = acc + ((delta == 0) ? 1.05f : 0.0f);
                    } else {
                        // 0.5*(MM + MM^T)[p][q],  MM = (I+A)^2 on slice t0
                        float mmpq = 0.0f, mmqp = 0.0f;
#pragma unroll
                        for (int j = 0; j < 9; j++) {
                            int dy = j / 3 - 1, dx = j % 3 - 1;
                            {   // p -> rn -> q
                                int rn = p + dy * 32 + dx;
                                int ddy = ey - dy, ddx = ex - dx;
                                if (rn >= 0 && rn < NB &&
                                    ddy >= -1 && ddy <= 1 && ddx >= -1 && ddx <= 1) {
                                    int j2 = (ddy + 1) * 3 + (ddx + 1);
                                    float a = sA0[(p - wbase) * 9 + j]   + ((j  == 4) ? 1.0f : 0.0f);
                                    float b = sA0[(rn - wbase) * 9 + j2] + ((j2 == 4) ? 1.0f : 0.0f);
                                    mmpq += a * b;
                                }
                            }
                            {   // q -> sn -> p
                                int sn = q + dy * 32 + dx;
                                int ddy = -ey - dy, ddx = -ex - dx;
                                if (sn >= 0 && sn < NB &&
                                    ddy >= -1 && ddy <= 1 && ddx >= -1 && ddx <= 1) {
                                    int j2 = (ddy + 1) * 3 + (ddx + 1);
                                    float a = sA0[(q - wbase) * 9 + j]   + ((j  == 4) ? 1.0f : 0.0f);
                                    float b = sA0[(sn - wbase) * 9 + j2] + ((j2 == 4) ? 1.0f : 0.0f);
                                    mmqp += a * b;
                                }
                            }
                        }
                        v = 0.5f * (mmpq + mmqp) +
                            ((delta == 0) ? ((i < 8) ? 1.05f : 0.05f) : 0.0f);
                    }
                    sBand[rr][delta + 66] = v;
                }
            } else if (s < 34) {
                // left offdiag (slice t0 = i-1): -0.5*(B + B^T)[p][q]
                int j = s - 25;
                int dy = j / 3 - 1, dx = j % 3 - 1;
                int delta = dy * 32 + dx;
                int q = p + delta;
                if (i > 0 && q >= 0 && q < NB) {
                    float add = (j == 4) ? 2.0f : 0.0f;
                    float v = -0.5f * (sA0[(p - wbase) * 9 + j] +
                                       sA0[(q - wbase) * 9 + (8 - j)] + add);
                    sBand[rr][136 + delta + 33] = v;
                }
            } else {
                // right offdiag (slice i): sA1 (12-node map) for 1<=i<=7, sA0 for i=0
                int j = s - 34;
                int dy = j / 3 - 1, dx = j % 3 - 1;
                int delta = dy * 32 + dx;
                int q = p + delta;
                if (i < 8 && q >= 0 && q < NB) {
                    float a, b;
                    if (i == 0) {
                        a = sA0[(p - wbase) * 9 + j];
                        b = sA0[(q - wbase) * 9 + (8 - j)];
                    } else {
                        int offp = p - p0 + 33;     // in {33,34}
                        int offq = q - p0 + 33;     // in [0,3]u[32,35]u[64,67]
                        int ip = (offp >> 5) * 4 + (offp & 31);
                        int iq = (offq >> 5) * 4 + (offq & 31);
                        a = sA1[ip * 9 + j];
                        b = sA1[iq * 9 + (8 - j)];
                    }
                    float add = (j == 4) ? 2.0f : 0.0f;
                    float v = -0.5f * (a + b + add);
                    sBand[rr][204 + delta + 33] = v;
                }
            }
        }
    }
    __syncthreads();

    // ---- 4) band blocks for own row ----
    {
        int p = p0 + rw;
        const float* bd = sBand[rw];
        int d0 = (col << 2) - p;

        {   // diag block i: D[d+66], valid d in [-66,66]
            float4 v = z;
            if (d0 + 3 >= -66 && d0 <= 66) {
                v.x = ((unsigned)(d0 + 66) <= 132u) ? bd[d0 + 66] : 0.0f;
                v.y = ((unsigned)(d0 + 67) <= 132u) ? bd[d0 + 67] : 0.0f;
                v.z = ((unsigned)(d0 + 68) <= 132u) ? bd[d0 + 68] : 0.0f;
                v.w = ((unsigned)(d0 + 69) <= 132u) ? bd[d0 + 69] : 0.0f;
            }
            __stcs(rowp + i * 256 + col, v);
        }
        if (i > 0) {                // left offdiag: L[d+33], d in [-33,33]
            float4 v = z;
            if (d0 + 3 >= -33 && d0 <= 33) {
                v.x = ((unsigned)(d0 + 33) <= 66u) ? bd[136 + d0 + 33] : 0.0f;
                v.y = ((unsigned)(d0 + 34) <= 66u) ? bd[136 + d0 + 34] : 0.0f;
                v.z = ((unsigned)(d0 + 35) <= 66u) ? bd[136 + d0 + 35] : 0.0f;
                v.w = ((unsigned)(d0 + 36) <= 66u) ? bd[136 + d0 + 36] : 0.0f;
            }
            __stcs(rowp + (i - 1) * 256 + col, v);
        }
        if (i < 8) {                // right offdiag: R[d+33]
            float4 v = z;
            if (d0 + 3 >= -33 && d0 <= 33) {
                v.x = ((unsigned)(d0 + 33) <= 66u) ? bd[204 + d0 + 33] : 0.0f;
                v.y = ((unsigned)(d0 + 34) <= 66u) ? bd[204 + d0 + 34] : 0.0f;
                v.z = ((unsigned)(d0 + 35) <= 66u) ? bd[204 + d0 + 35] : 0.0f;
                v.w = ((unsigned)(d0 + 36) <= 66u) ? bd[204 + d0 + 36] : 0.0f;
            }
            __stcs(rowp + (i + 1) * 256 + col, v);
        }
    }
}

// ---------------------------------------------------------------------------
// Launcher. Inputs: kappa, m, H, tau (unused). Output: fp32 [1, 9216, 9216].
// ---------------------------------------------------------------------------
extern "C" void kernel_launch(void* const* d_in, const int* in_sizes, int n_in,
                              void* d_out, int out_size) {
    const float* kappa = (const float*)d_in[0];
    const float* m     = (const float*)d_in[1];
    const float* H     = (const float*)d_in[2];
    float* out = (float*)d_out;

    k_all<<<TN / RPC, NTH>>>(kappa, m, H, out);
}

// round 16
// speedup vs baseline: 1.0438x; 1.0114x over previous
#include <cuda_runtime.h>
#include <cstddef>

#define NB 1024          // 32*32 nodes per time slice
#define NT 9
#define TN (NT * NB)     // 9216
#define W0MAX 134        // slice-t0 window nodes (p0-66 .. p0+67)
#define A1N 12           // slice-i window: 3 segments x 4 nodes
#define BSTRIDE 272      // per-row band: [0..135]=D(d+66), [136..203]=L(d+33), [204..271]=R(d+33)

// ---------------------------------------------------------------------------
// Per-node 9-point stencil coefficients of A at time slice ts.
// j = (dy+1)*3 + (dx+1); Dirichlet-invalid moves = exact 0.
// ---------------------------------------------------------------------------
__device__ __forceinline__ void coef9(const float* __restrict__ kappa,
                                      const float* __restrict__ m,
                                      const float* __restrict__ H,
                                      int n, int ts, float* c) {
    float kap = kappa[n * NT + ts];
    float k2  = kap * kap;
    float m1  = m[(0 * NB + n) * NT + ts];
    float m2  = m[(1 * NB + n) * NT + ts];
    float H11 = H[(0 * NB + n) * NT + ts];
    float H12 = H[(1 * NB + n) * NT + ts];
    float H22 = H[(3 * NB + n) * NT + ts];

    int ix = n & 31, iy = n >> 5;
    bool xm = ix > 0, xp = ix < 31, ym = iy > 0, yp = iy < 31;

    c[4] = k2 + 2.0f * H11 + 2.0f * H22;
    c[5] = xp         ? ( 0.5f * m1 - H11) : 0.0f;
    c[3] = xm         ? (-0.5f * m1 - H11) : 0.0f;
    c[7] = yp         ? ( 0.5f * m2 - H22) : 0.0f;
    c[1] = ym         ? (-0.5f * m2 - H22) : 0.0f;
    c[8] = (xp && yp) ? (-0.5f * H12)      : 0.0f;
    c[2] = (xp && ym) ? ( 0.5f * H12)      : 0.0f;
    c[6] = (xm && yp) ? ( 0.5f * H12)      : 0.0f;
    c[0] = (xm && ym) ? (-0.5f * H12)      : 0.0f;
}

// ---------------------------------------------------------------------------
// Single kernel, two independent CTA types on disjoint outputs (no flags,
// no inter-CTA waits). pair pc = bc>>1 covers rows {2pc, 2pc+1}.
//   even bc: ZERO CTA — streams the 6-7 non-band column blocks of both rows.
//            No smem, no barriers: stores are never gated.
//   odd  bc: BAND CTA — R11-validated window build + slot compute, then
//            streams the 3 band column blocks of both rows.
// Interleaving co-resides both types per SM so zero-stores cover band-CTA
// compute latency. Every output byte written exactly once.
// ---------------------------------------------------------------------------
__global__ __launch_bounds__(256)
void k_all(const float* __restrict__ kappa,
           const float* __restrict__ m,
           const float* __restrict__ H,
           float* __restrict__ out) {
    int bc  = blockIdx.x;               // 0..9215
    int pc  = bc >> 1;                  // row pair 0..4607
    int r0  = pc << 1;                  // first row
    int i   = r0 >> 10;                 // block row (pairs never straddle)
    int p0  = r0 & (NB - 1);
    int tid = threadIdx.x;
    float4 z = make_float4(0.f, 0.f, 0.f, 0.f);

    if ((bc & 1) == 0) {
        // ======================= ZERO CTA =======================
#pragma unroll
        for (int rr = 0; rr < 2; rr++) {
            float4* rowp = (float4*)(out + (size_t)(r0 + rr) * TN);
#pragma unroll
            for (int j = 0; j < 9; j++) {
                if (j < i - 1 || j > i + 1)
                    __stcs(rowp + j * 256 + tid, z);
            }
        }
        return;
    }

    // ======================= BAND CTA =======================
    __shared__ float sA0[W0MAX * 9];    // slice t0
    __shared__ float sA1[A1N * 9];      // slice i, 3 segments x 4 nodes
    __shared__ float sBand[2][BSTRIDE];

    int t0    = (i == 0) ? 0 : (i - 1);
    int wbase = max(0, p0 - 66);
    int whi   = min(NB, p0 + 1 + 67);
    int cnt0  = whi - wbase;
    bool needA1 = (i >= 1 && i <= 7);

    for (int k = tid; k < 2 * BSTRIDE; k += 256)
        ((float*)sBand)[k] = 0.0f;

    int tot = cnt0 + (needA1 ? A1N : 0);
    for (int k = tid; k < tot; k += 256) {
        float c[9];
        if (k < cnt0) {
            coef9(kappa, m, H, wbase + k, t0 + 1, c);
            float* dst = sA0 + k * 9;
#pragma unroll
            for (int j = 0; j < 9; j++) dst[j] = c[j];
        } else {
            int kk = k - cnt0;                  // 0..11
            int seg = kk >> 2;
            int node = p0 + seg * 32 - 33 + (kk & 3);
            float* dst = sA1 + kk * 9;
            if (node >= 0 && node < NB) {
                coef9(kappa, m, H, node, i + 1, c);
#pragma unroll
                for (int j = 0; j < 9; j++) dst[j] = c[j];
            } else {
#pragma unroll
                for (int j = 0; j < 9; j++) dst[j] = 0.0f;
            }
        }
    }
    __syncthreads();

    // ---- band slot computation (2 x 43 threads, disjoint warps) ----
    int rr = -1, s = 0;
    if (tid < 43)                    { rr = 0; s = tid; }
    else if (tid >= 64 && tid < 107) { rr = 1; s = tid - 64; }

    if (rr >= 0) {
        int p = p0 + rr;
        if (s < 25) {
            // diag slot: delta = ey*32 + ex
            int ey = s / 5 - 2, ex = s % 5 - 2;
            int delta = ey * 32 + ex;
            int q = p + delta;
            if (q >= 0 && q < NB) {
                float v;
                if (i == 0) {
                    // (A^T A)[p][q] = sum_r A[r][p]*A[r][q]
                    float acc = 0.0f;
#pragma unroll
                    for (int j = 0; j < 9; j++) {
                        int dy = j / 3 - 1, dx = j % 3 - 1;
                        int rn = p + dy * 32 + dx;
                        if (rn < 0 || rn >= NB) continue;
                        int ddy = ey - dy, ddx = ex - dx;
                        if (ddy < -1 || ddy > 1 || ddx < -1 || ddx > 1) continue;
                        int j2 = (ddy + 1) * 3 + (ddx + 1);
                        acc += sA0[(rn - wbase) * 9 + (8 - j)] *
                               sA0[(rn - wbase) * 9 + j2];
                    }
                    v = acc + ((delta == 0) ? 1.05f : 0.0f);
                } else {
                    // 0.5*(MM + MM^T)[p][q],  MM = (I+A)^2 on slice t0
                    float mmpq = 0.0f, mmqp = 0.0f;
#pragma unroll
                    for (int j = 0; j < 9; j++) {
                        int dy = j / 3 - 1, dx = j % 3 - 1;
                        {   // p -> rn -> q
                            int rn = p + dy * 32 + dx;
                            int ddy = ey - dy, ddx = ex - dx;
                            if (rn >= 0 && rn < NB &&
                                ddy >= -1 && ddy <= 1 && ddx >= -1 && ddx <= 1) {
                                int j2 = (ddy + 1) * 3 + (ddx + 1);
                                float a = sA0[(p - wbase) * 9 + j]   + ((j  == 4) ? 1.0f : 0.0f);
                                float b = sA0[(rn - wbase) * 9 + j2] + ((j2 == 4) ? 1.0f : 0.0f);
                                mmpq += a * b;
                            }
                        }
                        {   // q -> sn -> p
                            int sn = q + dy * 32 + dx;
                            int ddy = -ey - dy, ddx = -ex - dx;
                            if (sn >= 0 && sn < NB &&
                                ddy >= -1 && ddy <= 1 && ddx >= -1 && ddx <= 1) {
                                int j2 = (ddy + 1) * 3 + (ddx + 1);
                                float a = sA0[(q - wbase) * 9 + j]   + ((j  == 4) ? 1.0f : 0.0f);
                                float b = sA0[(sn - wbase) * 9 + j2] + ((j2 == 4) ? 1.0f : 0.0f);
                                mmqp += a * b;
                            }
                        }
                    }
                    v = 0.5f * (mmpq + mmqp) +
                        ((delta == 0) ? ((i < 8) ? 1.05f : 0.05f) : 0.0f);
                }
                sBand[rr][delta + 66] = v;
            }
        } else if (s < 34) {
            // left offdiag (slice t0 = i-1): -0.5*(B + B^T)[p][q]
            int j = s - 25;
            int dy = j / 3 - 1, dx = j % 3 - 1;
            int delta = dy * 32 + dx;
            int q = p + delta;
            if (i > 0 && q >= 0 && q < NB) {
                float add = (j == 4) ? 2.0f : 0.0f;
                float v = -0.5f * (sA0[(p - wbase) * 9 + j] +
                                   sA0[(q - wbase) * 9 + (8 - j)] + add);
                sBand[rr][136 + delta + 33] = v;
            }
        } else {
            // right offdiag (slice i): sA1 (12-node map) for 1<=i<=7, sA0 for i=0
            int j = s - 34;
            int dy = j / 3 - 1, dx = j % 3 - 1;
            int delta = dy * 32 + dx;
            int q = p + delta;
            if (i < 8 && q >= 0 && q < NB) {
                float a, b;
                if (i == 0) {
                    a = sA0[(p - wbase) * 9 + j];
                    b = sA0[(q - wbase) * 9 + (8 - j)];
                } else {
                    int offp = p - p0 + 33;     // in {33,34}
                    int offq = q - p0 + 33;     // in [0,3]u[32,35]u[64,67]
                    int ip = (offp >> 5) * 4 + (offp & 31);
                    int iq = (offq >> 5) * 4 + (offq & 31);
                    a = sA1[ip * 9 + j];
                    b = sA1[iq * 9 + (8 - j)];
                }
                float add = (j == 4) ? 2.0f : 0.0f;
                float v = -0.5f * (a + b + add);
                sBand[rr][204 + delta + 33] = v;
            }
        }
    }
    __syncthreads();

    // ---- band blocks for both rows ----
    int q0 = tid << 2;
#pragma unroll
    for (int rr2 = 0; rr2 < 2; rr2++) {
        int p = p0 + rr2;
        float4* rowp = (float4*)(out + (size_t)(r0 + rr2) * TN);
        const float* bd = sBand[rr2];
        int d0 = q0 - p;

        {   // diag block i: D[d+66], valid d in [-66,66]
            float4 v = z;
            if (d0 + 3 >= -66 && d0 <= 66) {
                v.x = ((unsigned)(d0 + 66) <= 132u) ? bd[d0 + 66] : 0.0f;
                v.y = ((unsigned)(d0 + 67) <= 132u) ? bd[d0 + 67] : 0.0f;
                v.z = ((unsigned)(d0 + 68) <= 132u) ? bd[d0 + 68] : 0.0f;
                v.w = ((unsigned)(d0 + 69) <= 132u) ? bd[d0 + 69] : 0.0f;
            }
            __stcs(rowp + i * 256 + tid, v);
        }
        if (i > 0) {                // left offdiag: L[d+33], d in [-33,33]
            float4 v = z;
            if (d0 + 3 >= -33 && d0 <= 33) {
                v.x = ((unsigned)(d0 + 33) <= 66u) ? bd[136 + d0 + 33] : 0.0f;
                v.y = ((unsigned)(d0 + 34) <= 66u) ? bd[136 + d0 + 34] : 0.0f;
                v.z = ((unsigned)(d0 + 35) <= 66u) ? bd[136 + d0 + 35] : 0.0f;
                v.w = ((unsigned)(d0 + 36) <= 66u) ? bd[136 + d0 + 36] : 0.0f;
            }
            __stcs(rowp + (i - 1) * 256 + tid, v);
        }
        if (i < 8) {                // right offdiag: R[d+33]
            float4 v = z;
            if (d0 + 3 >= -33 && d0 <= 33) {
                v.x = ((unsigned)(d0 + 33) <= 66u) ? bd[204 + d0 + 33] : 0.0f;
                v.y = ((unsigned)(d0 + 34) <= 66u) ? bd[204 + d0 + 34] : 0.0f;
                v.z = ((unsigned)(d0 + 35) <= 66u) ? bd[204 + d0 + 35] : 0.0f;
                v.w = ((unsigned)(d0 + 36) <= 66u) ? bd[204 + d0 + 36] : 0.0f;
            }
            __stcs(rowp + (i + 1) * 256 + tid, v);
        }
    }
}

// ---------------------------------------------------------------------------
// Launcher. Inputs: kappa, m, H, tau (unused). Output: fp32 [1, 9216, 9216].
// ---------------------------------------------------------------------------
extern "C" void kernel_launch(void* const* d_in, const int* in_sizes, int n_in,
                              void* d_out, int out_size) {
    const float* kappa = (const float*)d_in[0];
    const float* m     = (const float*)d_in[1];
    const float* H     = (const float*)d_in[2];
    float* out = (float*)d_out;

    k_all<<<TN, 256>>>(kappa, m, H, out);   // 2 CTAs per row pair
}